// round 1
// baseline (speedup 1.0000x reference)
#include <cuda_runtime.h>
#include <cstddef>

#define TSTEPS 1024
#define BATCH  64
#define DIN    256
#define DHID   256
#define NC     1024          // 4 * DHID (gate columns, packed order)
#define NCTA   128           // recurrent CTAs (each owns 2 hidden units)
#define NTHR   128
#define M_TOTAL (TSTEPS * BATCH)

// ------------------------- device scratch (static, no allocs) -------------------------
__device__ float    g_xp[(size_t)M_TOTAL * NC];   // x-projections + bias, [t*B + b][c'] (268 MB)
__device__ float    g_Wxp[DIN * NC];              // packed Wx  [k][c']
__device__ float    g_Whp[DHID * NC];             // packed Wh  [k][c']
__device__ float    g_bp[NC];                     // packed bias [c']
__device__ float    g_hT[2][DHID * BATCH];        // double-buffered h, transposed [j][b]
__device__ unsigned g_flags[NCTA];                // per-CTA step counters (barrier)

// ------------------------- pack weights + reset flags -------------------------
// c' = cta*8 + gate*2 + jj ; cta owns hidden units j0 = cta*2 .. cta*2+1
__global__ void pack_kernel(const float* __restrict__ Wf, const float* __restrict__ bf,
                            const float* __restrict__ Wi, const float* __restrict__ bi,
                            const float* __restrict__ Wg, const float* __restrict__ bg,
                            const float* __restrict__ Wo, const float* __restrict__ bo)
{
    int idx = blockIdx.x * blockDim.x + threadIdx.x;
    if (blockIdx.x == 0 && threadIdx.x < NCTA) g_flags[threadIdx.x] = 0u;
    if (idx >= DIN * NC) return;
    int k    = idx >> 10;       // / NC
    int c    = idx & (NC - 1);
    int cta  = c >> 3;
    int slot = c & 7;
    int gate = slot >> 1;
    int jj   = slot & 1;
    int j    = cta * 2 + jj;
    const float* W = (gate == 0) ? Wf : (gate == 1) ? Wi : (gate == 2) ? Wg : Wo;
    const float* b = (gate == 0) ? bf : (gate == 1) ? bi : (gate == 2) ? bg : bo;
    g_Wxp[idx] = W[(size_t)k * DHID + j];            // rows 0..255 : x part
    g_Whp[idx] = W[(size_t)(DIN + k) * DHID + j];    // rows 256..511 : h part
    if (k == 0) g_bp[c] = b[j];
}

// ------------------------- xproj GEMM: g_xp = X @ g_Wxp + g_bp -------------------------
// M = 65536, K = 256, N = 1024. Tile 128x64, 256 threads, 8x4 micro-tile, fp32.
__global__ __launch_bounds__(256) void xproj_kernel(const float* __restrict__ X)
{
    __shared__ float As[16][132];   // [k][m], padded (132*4 % 16 == 0, keeps float4 align)
    __shared__ float Bs[16][64];    // [k][n]

    const int tid = threadIdx.x;
    const int m0  = blockIdx.y * 128;
    const int n0  = blockIdx.x * 64;
    const int ty  = tid >> 4;       // 0..15 -> 8 rows each
    const int tx  = tid & 15;       // 0..15 -> 4 cols each

    float acc[8][4] = {};

    for (int k0 = 0; k0 < DIN; k0 += 16) {
        // A tile: 128 rows x 16 k  (512 float4, 2 per thread), store transposed
        #pragma unroll
        for (int i = 0; i < 2; i++) {
            int L  = tid + i * 256;
            int m  = L >> 2;
            int kq = L & 3;
            float4 v = *(const float4*)&X[(size_t)(m0 + m) * DIN + k0 + kq * 4];
            As[kq * 4 + 0][m] = v.x;
            As[kq * 4 + 1][m] = v.y;
            As[kq * 4 + 2][m] = v.z;
            As[kq * 4 + 3][m] = v.w;
        }
        // B tile: 16 k x 64 n (256 float4, 1 per thread)
        {
            int kk = tid >> 4;
            int nq = tid & 15;
            *(float4*)&Bs[kk][nq * 4] =
                *(const float4*)&g_Wxp[(size_t)(k0 + kk) * NC + n0 + nq * 4];
        }
        __syncthreads();

        #pragma unroll
        for (int kk = 0; kk < 16; kk++) {
            float a[8], b[4];
            *(float4*)&a[0] = *(const float4*)&As[kk][ty * 8];
            *(float4*)&a[4] = *(const float4*)&As[kk][ty * 8 + 4];
            *(float4*)&b[0] = *(const float4*)&Bs[kk][tx * 4];
            #pragma unroll
            for (int i = 0; i < 8; i++)
                #pragma unroll
                for (int j = 0; j < 4; j++)
                    acc[i][j] += a[i] * b[j];
        }
        __syncthreads();
    }

    float4 bias = *(const float4*)&g_bp[n0 + tx * 4];
    #pragma unroll
    for (int i = 0; i < 8; i++) {
        float4 o;
        o.x = acc[i][0] + bias.x;
        o.y = acc[i][1] + bias.y;
        o.z = acc[i][2] + bias.z;
        o.w = acc[i][3] + bias.w;
        *(float4*)&g_xp[(size_t)(m0 + ty * 8 + i) * NC + n0 + tx * 4] = o;
    }
}

// ------------------------- persistent recurrent kernel -------------------------
// 128 CTAs x 128 threads, all co-resident. CTA cta owns hidden units {2cta, 2cta+1}
// across all 4 gates (8 packed columns) and keeps their cell state in smem.
__global__ __launch_bounds__(NTHR) void recur_kernel(float* __restrict__ out, int out_size)
{
    extern __shared__ float sm[];
    float* hs   = sm;             // 16384 floats, h_{t-1} as [k][b]
    float* gbuf = sm + DHID * BATCH;       // 512 floats: [gate][b][jj]
    float* cs   = gbuf + 4 * BATCH * 2;    // 128 floats: cell state [b*2 + jj]
    __shared__ float ws[DHID * 8];         // Wh slice [k][slot]

    const int tid = threadIdx.x;
    const int cta = blockIdx.x;
    const int bp  = tid >> 2;      // 0..31 (row pair: b = 2bp, 2bp+1)
    const int gat = tid & 3;       // 0..3  (gate)
    const int j0  = cta * 2;

    for (int i = tid; i < DHID * 8; i += NTHR) {
        int k = i >> 3, slot = i & 7;
        ws[i] = g_Whp[(size_t)k * NC + cta * 8 + slot];
    }
    cs[tid] = 0.0f;
    __syncthreads();

    const size_t HT_OFF = (size_t)TSTEPS * BATCH * DHID;

    for (int t = 0; t < TSTEPS; t++) {
        float acc00 = 0.f, acc01 = 0.f, acc10 = 0.f, acc11 = 0.f;  // [bi][jj]

        if (t > 0) {
            // stage h_{t-1} (already transposed [j][b] in global) into smem
            const float4* src = (const float4*)g_hT[(t - 1) & 1];
            float4*       dst = (float4*)hs;
            for (int i = tid; i < (DHID * BATCH) / 4; i += NTHR) dst[i] = src[i];
            __syncthreads();

            #pragma unroll 8
            for (int k = 0; k < DHID; k++) {
                float2 h2 = *(const float2*)&hs[k * BATCH + bp * 2];
                float2 w2 = *(const float2*)&ws[k * 8 + gat * 2];
                acc00 += h2.x * w2.x;
                acc01 += h2.x * w2.y;
                acc10 += h2.y * w2.x;
                acc11 += h2.y * w2.y;
            }
        }

        // add x-projection (bias already folded in)
        size_t xbase = ((size_t)t * BATCH + bp * 2) * NC + cta * 8 + gat * 2;
        float2 x0 = *(const float2*)&g_xp[xbase];
        float2 x1 = *(const float2*)&g_xp[xbase + NC];

        gbuf[gat * 128 + (bp * 2 + 0) * 2 + 0] = acc00 + x0.x;
        gbuf[gat * 128 + (bp * 2 + 0) * 2 + 1] = acc01 + x0.y;
        gbuf[gat * 128 + (bp * 2 + 1) * 2 + 0] = acc10 + x1.x;
        gbuf[gat * 128 + (bp * 2 + 1) * 2 + 1] = acc11 + x1.y;
        __syncthreads();

        // combine: one thread per (b, jj)
        {
            int b  = tid >> 1;
            int jj = tid & 1;
            int idx = b * 2 + jj;
            float fv = gbuf[0 * 128 + idx];
            float iv = gbuf[1 * 128 + idx];
            float gv = gbuf[2 * 128 + idx];
            float ov = gbuf[3 * 128 + idx];
            fv = 1.0f / (1.0f + __expf(-fv));
            iv = 1.0f / (1.0f + __expf(-iv));
            ov = 1.0f / (1.0f + __expf(-ov));
            gv = tanhf(gv);
            float c = fv * cs[idx] + iv * gv;
            cs[idx] = c;
            float h = ov * tanhf(c);
            int j = j0 + jj;
            out[(size_t)t * (BATCH * DHID) + (size_t)b * DHID + j] = h;
            g_hT[t & 1][j * BATCH + b] = h;
            if (t == TSTEPS - 1) {
                if ((size_t)out_size >= HT_OFF + (size_t)BATCH * DHID)
                    out[HT_OFF + (size_t)b * DHID + j] = h;
                if ((size_t)out_size >= HT_OFF + 2 * (size_t)BATCH * DHID)
                    out[HT_OFF + (size_t)BATCH * DHID + (size_t)b * DHID + j] = c;
            }
        }

        // ---- grid-wide barrier (flag array, monotonic counters) ----
        __threadfence();
        __syncthreads();
        if (tid == 0) atomicExch(&g_flags[cta], (unsigned)(t + 1));
        {
            const unsigned want = (unsigned)(t + 1);
            volatile unsigned* vf = g_flags;
            while (vf[tid] < want) { }
        }
        __threadfence();
        __syncthreads();
    }
}

// ------------------------- launch -------------------------
extern "C" void kernel_launch(void* const* d_in, const int* in_sizes, int n_in,
                              void* d_out, int out_size)
{
    const float* X  = (const float*)d_in[0];
    const float* Wf = (const float*)d_in[1];
    const float* bf = (const float*)d_in[2];
    const float* Wi = (const float*)d_in[3];
    const float* bi = (const float*)d_in[4];
    const float* Wg = (const float*)d_in[5];
    const float* bg = (const float*)d_in[6];
    const float* Wo = (const float*)d_in[7];
    const float* bo = (const float*)d_in[8];
    float* out = (float*)d_out;

    const int smem_bytes = (DHID * BATCH + 4 * BATCH * 2 + NTHR) * (int)sizeof(float);
    cudaFuncSetAttribute(recur_kernel, cudaFuncAttributeMaxDynamicSharedMemorySize, smem_bytes);

    pack_kernel<<<(DIN * NC + 255) / 256, 256>>>(Wf, bf, Wi, bi, Wg, bg, Wo, bo);

    dim3 ggrid(NC / 64, M_TOTAL / 128);
    xproj_kernel<<<ggrid, 256>>>(X);

    recur_kernel<<<NCTA, NTHR, smem_bytes>>>(out, out_size);
}

// round 2
// speedup vs baseline: 1.8534x; 1.8534x over previous
#include <cuda_runtime.h>
#include <cstddef>

#define TSTEPS 1024
#define BATCH  64
#define DIN    256
#define DHID   256
#define NC     1024           // 4 * DHID packed gate columns
#define M_TOTAL (TSTEPS * BATCH)

#define CLUSTER 8             // CTAs per cluster (column partitions)
#define NGROUP  16            // batch groups (4 batches each)
#define NCTA    (CLUSTER * NGROUP)   // 128
#define RTHR    512           // threads in recur kernel

// ------------------------- device scratch (static, no allocs) -------------------------
__device__ float g_xp[(size_t)M_TOTAL * NC];   // x-proj + bias, [t*B + b][pc]
__device__ float g_Wxp[DIN * NC];              // packed Wx [k][pc]   (for xproj GEMM)
__device__ float g_Whp[DHID * NC];             // packed Wh [part][kc][i][c] (for register load)
__device__ float g_bp[NC];                     // packed bias [pc]

// packed column: pc = (j>>5)*128 + (j&31)*4 + gate   (j = hidden unit, gate in {f,i,g,o})

// ------------------------- pack weights -------------------------
__global__ void pack_kernel(const float* __restrict__ Wf, const float* __restrict__ bf,
                            const float* __restrict__ Wi, const float* __restrict__ bi,
                            const float* __restrict__ Wg, const float* __restrict__ bg,
                            const float* __restrict__ Wo, const float* __restrict__ bo)
{
    int idx = blockIdx.x * blockDim.x + threadIdx.x;
    if (idx >= DIN * NC) return;
    int k    = idx >> 10;          // 0..255
    int pc   = idx & (NC - 1);     // 0..1023
    int part = pc >> 7;            // 0..7
    int c    = pc & 127;           // 0..127
    int u    = c >> 2;             // 0..31
    int gate = c & 3;              // 0..3
    int j    = part * 32 + u;
    const float* W = (gate == 0) ? Wf : (gate == 1) ? Wi : (gate == 2) ? Wg : Wo;
    const float* b = (gate == 0) ? bf : (gate == 1) ? bi : (gate == 2) ? bg : bo;
    // Wx for xproj GEMM, [k][pc]
    g_Wxp[idx] = W[(size_t)k * DHID + j];
    // Wh for recur register preload, coalesced layout [part][kc][i][c]
    int kc = k >> 6, i = k & 63;
    g_Whp[(size_t)(((part * 4 + kc) * 64) + i) * 128 + c] = W[(size_t)(DIN + k) * DHID + j];
    if (k == 0) g_bp[pc] = b[j];
}

// ------------------------- xproj GEMM: g_xp = X @ g_Wxp + g_bp -------------------------
// M=65536, K=256, N=1024. 128x64 tile, 256 threads, 8x4 micro-tile, fma.rn.f32x2.
__global__ __launch_bounds__(256) void xproj_kernel(const float* __restrict__ X)
{
    __shared__ float As[16][132];   // [k][m] transposed, padded
    __shared__ __align__(16) float Bs[16][64];    // [k][n]

    const int tid = threadIdx.x;
    const int m0  = blockIdx.y * 128;
    const int n0  = blockIdx.x * 64;
    const int ty  = tid >> 4;       // 0..15 -> 8 rows
    const int tx  = tid & 15;       // 0..15 -> 4 cols (2 f32x2 pairs)

    unsigned long long acc2[8][2];
    #pragma unroll
    for (int i = 0; i < 8; i++) { acc2[i][0] = 0ull; acc2[i][1] = 0ull; }

    for (int k0 = 0; k0 < DIN; k0 += 16) {
        #pragma unroll
        for (int i = 0; i < 2; i++) {
            int L  = tid + i * 256;
            int m  = L >> 2;
            int kq = L & 3;
            float4 v = *(const float4*)&X[(size_t)(m0 + m) * DIN + k0 + kq * 4];
            As[kq * 4 + 0][m] = v.x;
            As[kq * 4 + 1][m] = v.y;
            As[kq * 4 + 2][m] = v.z;
            As[kq * 4 + 3][m] = v.w;
        }
        {
            int kk = tid >> 4;
            int nq = tid & 15;
            *(float4*)&Bs[kk][nq * 4] =
                *(const float4*)&g_Wxp[(size_t)(k0 + kk) * NC + n0 + nq * 4];
        }
        __syncthreads();

        #pragma unroll
        for (int kk = 0; kk < 16; kk++) {
            float a[8];
            *(float4*)&a[0] = *(const float4*)&As[kk][ty * 8];
            *(float4*)&a[4] = *(const float4*)&As[kk][ty * 8 + 4];
            ulonglong2 bb = *(const ulonglong2*)&Bs[kk][tx * 4];   // (b0,b1),(b2,b3)
            #pragma unroll
            for (int i = 0; i < 8; i++) {
                unsigned long long aa;
                asm("mov.b64 %0, {%1, %1};" : "=l"(aa) : "f"(a[i]));
                asm("fma.rn.f32x2 %0, %1, %2, %0;" : "+l"(acc2[i][0]) : "l"(aa), "l"(bb.x));
                asm("fma.rn.f32x2 %0, %1, %2, %0;" : "+l"(acc2[i][1]) : "l"(aa), "l"(bb.y));
            }
        }
        __syncthreads();
    }

    float4 bias = *(const float4*)&g_bp[n0 + tx * 4];
    #pragma unroll
    for (int i = 0; i < 8; i++) {
        float r0, r1, r2, r3;
        asm("mov.b64 {%0, %1}, %2;" : "=f"(r0), "=f"(r1) : "l"(acc2[i][0]));
        asm("mov.b64 {%0, %1}, %2;" : "=f"(r2), "=f"(r3) : "l"(acc2[i][1]));
        float4 o;
        o.x = r0 + bias.x;
        o.y = r1 + bias.y;
        o.z = r2 + bias.z;
        o.w = r3 + bias.w;
        *(float4*)&g_xp[(size_t)(m0 + ty * 8 + i) * NC + n0 + tx * 4] = o;
    }
}

// ------------------------- recurrent kernel: 16 independent clusters of 8 -------------------------
// Cluster g owns batches 4g..4g+3. CTA (rank r) owns hidden units r*32..r*32+31 (all gates).
// Weights live in registers (64 floats/thread). h exchanged via DSMEM, one cluster.sync/step.
__global__ void __cluster_dims__(CLUSTER, 1, 1) __launch_bounds__(RTHR, 1)
recur_kernel(float* __restrict__ out, int out_size)
{
    __shared__ __align__(16) float hbuf[2][DHID * 4];      // [buf][k*4 + b]  (8 KB)
    __shared__ __align__(16) float pbuf[4][4][128];        // [kc][b][c] partial dots (8 KB)

    const int tid  = threadIdx.x;
    const int part = blockIdx.x & (CLUSTER - 1);   // == cluster rank
    const int grp  = blockIdx.x >> 3;
    const int kc   = tid >> 7;       // 0..3  (k chunk of 64)
    const int c    = tid & 127;      // 0..127 (local packed column)

    // ---- preload Wh slice into registers (coalesced) ----
    float w[64];
    {
        const float* src = &g_Whp[(size_t)((part * 4 + kc) * 64) * 128 + c];
        #pragma unroll
        for (int i = 0; i < 64; i++) w[i] = src[(size_t)i * 128];
    }

    // zero h buffers
    for (int i = tid; i < 2 * DHID * 4; i += RTHR) ((float*)hbuf)[i] = 0.0f;

    // combiner state (threads 0..127): b = tid>>5, u = tid&31
    const int cb = tid >> 5;         // batch within group
    const int cu = tid & 31;         // hidden unit within part
    const int bg = grp * 4 + cb;     // global batch
    const int j  = part * 32 + cu;   // global hidden unit
    float cstate = 0.0f;

    // byte offset (within shared window) of hbuf for DSMEM stores
    unsigned hbuf_base;
    asm("{ .reg .u64 t; cvta.to.shared.u64 t, %1; cvt.u32.u64 %0, t; }"
        : "=r"(hbuf_base) : "l"((void*)hbuf));

    __syncthreads();

    const size_t HT_OFF = (size_t)TSTEPS * BATCH * DHID;

    for (int t = 0; t < TSTEPS; t++) {
        const int p = t & 1;

        // prefetch x-projection for the combine stage (independent of h)
        float4 xp4;
        if (tid < 128)
            xp4 = *(const float4*)&g_xp[((size_t)t * BATCH + bg) * NC + part * 128 + cu * 4];

        // ---- stage 1: partial dots, 4 batches via fma.rn.f32x2 ----
        {
            unsigned long long acc01 = 0ull, acc23 = 0ull;
            const float* hrow = &hbuf[p][kc * 64 * 4];
            #pragma unroll
            for (int i = 0; i < 64; i++) {
                ulonglong2 hh = *(const ulonglong2*)&hrow[i * 4];  // (h0,h1),(h2,h3) at k
                unsigned long long ww;
                asm("mov.b64 %0, {%1, %1};" : "=l"(ww) : "f"(w[i]));
                asm("fma.rn.f32x2 %0, %1, %2, %0;" : "+l"(acc01) : "l"(ww), "l"(hh.x));
                asm("fma.rn.f32x2 %0, %1, %2, %0;" : "+l"(acc23) : "l"(ww), "l"(hh.y));
            }
            float a0, a1, a2, a3;
            asm("mov.b64 {%0, %1}, %2;" : "=f"(a0), "=f"(a1) : "l"(acc01));
            asm("mov.b64 {%0, %1}, %2;" : "=f"(a2), "=f"(a3) : "l"(acc23));
            pbuf[kc][0][c] = a0;
            pbuf[kc][1][c] = a1;
            pbuf[kc][2][c] = a2;
            pbuf[kc][3][c] = a3;
        }
        __syncthreads();

        // ---- stage 2: combine (threads 0..127) ----
        if (tid < 128) {
            float4 s = make_float4(0.f, 0.f, 0.f, 0.f);
            #pragma unroll
            for (int q = 0; q < 4; q++) {
                float4 p4 = *(const float4*)&pbuf[q][cb][cu * 4];
                s.x += p4.x; s.y += p4.y; s.z += p4.z; s.w += p4.w;
            }
            float fv = s.x + xp4.x;
            float iv = s.y + xp4.y;
            float gv = s.z + xp4.z;
            float ov = s.w + xp4.w;
            fv = 1.0f / (1.0f + __expf(-fv));
            iv = 1.0f / (1.0f + __expf(-iv));
            ov = 1.0f / (1.0f + __expf(-ov));
            float gt, ht;
            asm("tanh.approx.f32 %0, %1;" : "=f"(gt) : "f"(gv));
            cstate = fv * cstate + iv * gt;
            asm("tanh.approx.f32 %0, %1;" : "=f"(ht) : "f"(cstate));
            float h = ov * ht;

            // output
            out[(size_t)t * (BATCH * DHID) + (size_t)bg * DHID + j] = h;
            if (t == TSTEPS - 1) {
                if ((size_t)out_size >= HT_OFF + (size_t)BATCH * DHID)
                    out[HT_OFF + (size_t)bg * DHID + j] = h;
                if ((size_t)out_size >= HT_OFF + 2 * (size_t)BATCH * DHID)
                    out[HT_OFF + (size_t)BATCH * DHID + (size_t)bg * DHID + j] = cstate;
            }

            // broadcast h to all 8 CTAs' hbuf[1-p] via DSMEM
            unsigned dst = hbuf_base + (unsigned)(((1 - p) * DHID * 4 + j * 4 + cb) * 4);
            #pragma unroll
            for (int r = 0; r < CLUSTER; r++) {
                unsigned rem;
                asm("mapa.shared::cluster.u32 %0, %1, %2;" : "=r"(rem) : "r"(dst), "r"(r));
                asm volatile("st.shared::cluster.f32 [%0], %1;" :: "r"(rem), "f"(h) : "memory");
            }
        }

        // ---- stage 3: cluster barrier (orders DSMEM writes + pbuf reuse) ----
        asm volatile("barrier.cluster.arrive.aligned;" ::: "memory");
        asm volatile("barrier.cluster.wait.aligned;" ::: "memory");
    }
}

// ------------------------- launch -------------------------
extern "C" void kernel_launch(void* const* d_in, const int* in_sizes, int n_in,
                              void* d_out, int out_size)
{
    const float* X  = (const float*)d_in[0];
    const float* Wf = (const float*)d_in[1];
    const float* bf = (const float*)d_in[2];
    const float* Wi = (const float*)d_in[3];
    const float* bi = (const float*)d_in[4];
    const float* Wg = (const float*)d_in[5];
    const float* bg = (const float*)d_in[6];
    const float* Wo = (const float*)d_in[7];
    const float* bo = (const float*)d_in[8];
    float* out = (float*)d_out;

    pack_kernel<<<(DIN * NC + 255) / 256, 256>>>(Wf, bf, Wi, bi, Wg, bg, Wo, bo);

    dim3 ggrid(NC / 64, M_TOTAL / 128);
    xproj_kernel<<<ggrid, 256>>>(X);

    recur_kernel<<<NCTA, RTHR>>>(out, out_size);
}